// round 11
// baseline (speedup 1.0000x reference)
#include <cuda_runtime.h>
#include <cuda_bf16.h>
#include <math.h>

// Oscillator: XLA rw16 cumsum association + div.full.f32 scale chain (bit-exact
// through x); MUFU sin. Single persistent kernel: prep phase (64 blocks) +
// device grid barrier + grid-stride oscillator phase. Grid sized for provable
// full co-residency (148 SMs x 8 blocks, launch_bounds caps regs/smem).

#define B_DIM 64
#define F_DIM 4096
#define NHOPS (B_DIM * F_DIM)          // 262144
#define NOUT (NHOPS * 64)              // 16777216
#define NQ 16384                       // strips of 16 per row
#define TPB 256
#define GRID (148 * 8)                 // 1184, all co-resident by construction
#define NTILES (NOUT / 4 / TPB)        // 16384 tiles of 256 float4

__device__ float    g_R1z[B_DIM * NQ]; // zero-shifted strip offsets
__device__ float4   g_b4[NHOPS];       // per hop: (f, fold4, fold8, fold12)
__device__ unsigned g_done;            // prep blocks completed (reset each call)
__device__ unsigned g_fin;             // blocks finished (reset each call)

__device__ __forceinline__ float div_full(float a, float b) {
    float r;
    asm("div.full.f32 %0, %1, %2;" : "=f"(r) : "f"(a), "f"(b));
    return r;
}

__global__ void __launch_bounds__(TPB, 8) fused_k(const float* __restrict__ freq,
                                                  const float* __restrict__ pmod,
                                                  float* __restrict__ out) {
    __shared__ float sm16[4096];
    __shared__ float S1[1024];
    __shared__ float R2s[1024];
    __shared__ float S2[64];
    __shared__ float I3s[64];
    __shared__ float R3s[64];
    __shared__ float R4s[4];

    const int tid = threadIdx.x;

    // ---------------- Phase A: rw16 scan tables (blocks 0..63, one row each) ----
    if (blockIdx.x < B_DIM) {
        const int row = blockIdx.x;
        const float* fr = freq + row * F_DIM;

        for (int j = tid; j < 4096; j += TPB) {
            float f = fr[j];
            float s = 0.0f, c4 = 0.0f, c8 = 0.0f, c12 = 0.0f;
            #pragma unroll
            for (int i = 0; i < 16; i++) {
                s = __fadd_rn(s, f);
                if (i == 3)  c4  = s;
                if (i == 7)  c8  = s;
                if (i == 11) c12 = s;
            }
            sm16[j] = s;
            g_b4[row * F_DIM + j] = make_float4(f, c4, c8, c12);
        }
        __syncthreads();

        // strip totals S1[a] (V1[b] = sm16[b/4])
        for (int a = tid; a < 1024; a += TPB) {
            float acc = 0.0f;
            #pragma unroll
            for (int i = 0; i < 16; i++) acc = __fadd_rn(acc, sm16[4 * a + (i >> 2)]);
            S1[a] = acc;
        }
        __syncthreads();

        if (tid < 64) {
            float acc = 0.0f;
            #pragma unroll
            for (int i = 0; i < 16; i++) acc = __fadd_rn(acc, S1[16 * tid + i]);
            S2[tid] = acc;
        }
        __syncthreads();

        if (tid < 4) {
            float acc = 0.0f;
            #pragma unroll
            for (int i = 0; i < 16; i++) {
                acc = __fadd_rn(acc, S2[16 * tid + i]);
                I3s[16 * tid + i] = acc;
            }
        }
        __syncthreads();
        if (tid == 0) {
            float acc = 0.0f;
            #pragma unroll
            for (int d = 0; d < 4; d++) {
                acc = __fadd_rn(acc, I3s[16 * d + 15]);
                R4s[d] = acc;
            }
            g_R1z[row * NQ] = 0.0f;    // zero-shift entry
        }
        __syncthreads();
        if (tid < 64)
            R3s[tid] = (tid >= 16) ? __fadd_rn(I3s[tid], R4s[(tid >> 4) - 1]) : I3s[tid];
        __syncthreads();
        if (tid < 64) {
            float acc = 0.0f;
            #pragma unroll
            for (int i = 0; i < 16; i++) {
                acc = __fadd_rn(acc, S1[16 * tid + i]);
                R2s[16 * tid + i] = (tid > 0) ? __fadd_rn(acc, R3s[tid - 1]) : acc;
            }
        }
        __syncthreads();
        // R1[q] = fl(I1[q] + R2[q/16-1]) -> zero-shifted global (recompute I1)
        for (int a = tid; a < 1024; a += TPB) {
            float off = (a > 0) ? R2s[a - 1] : 0.0f;
            float acc = 0.0f;
            float* dst = g_R1z + row * NQ + 16 * a + 1;
            #pragma unroll
            for (int i = 0; i < 16; i++) {
                acc = __fadd_rn(acc, sm16[4 * a + (i >> 2)]);
                float v = (a > 0) ? __fadd_rn(acc, off) : acc;
                if (16 * a + i < NQ - 1) dst[i] = v;
            }
        }
        __threadfence();
        __syncthreads();
        if (tid == 0) atomicAdd(&g_done, 1u);
    }

    // ---------------- grid barrier: wait for all 64 prep blocks --------------
    if (tid == 0) {
        unsigned v;
        do {
            asm volatile("ld.global.acquire.gpu.u32 %0, [%1];" : "=r"(v) : "l"(&g_done));
            if (v < (unsigned)B_DIM) __nanosleep(128);
        } while (v < (unsigned)B_DIM);
    }
    __syncthreads();

    // ---------------- Phase B: oscillator, grid-stride over tiles ------------
    const float TWO_PI_F = 6.2831853071795864769f;     // 0x40C90FDB
    const float TWO_O_PI = 0.63661977236758134308f;
    const float MAGIC    = 12582912.0f;                // 1.5 * 2^23
    const float P1 = 1.57079637050628662109375f;       // fl32(pi/2)
    const float P2 = -4.37113900018624283e-08f;        // pi/2 - P1

    for (int tile = blockIdx.x; tile < NTILES; tile += GRID) {
        const int gq  = tile * TPB + tid;              // float4 index
        const int hop = gq >> 4;
        const int s   = gq & 15;
        const int row = gq >> 16;                      // 65536 float4 per row

        const float4 b4 = __ldg(&g_b4[hop]);           // (f, c4, c8, c12)
        const float  f  = b4.x;
        const float  f0 = __ldg(freq + (row << 12));   // cs[0] = f_0
        const float  R1v = __ldg(&g_R1z[row * NQ + ((gq >> 2) & (NQ - 1))]);
        const float4 p4 = __ldg((const float4*)pmod + gq);

        const int s3 = s & 3;
        float aa = (s3 & 1) ? b4.y : 0.0f;
        float bb = (s3 & 1) ? b4.w : b4.z;
        float sm = (s3 & 2) ? bb : aa;

        float pm[4] = {p4.x, p4.y, p4.z, p4.w};
        float ov[4];
        #pragma unroll
        for (int l = 0; l < 4; l++) {
            sm = __fadd_rn(sm, f);                     // I0[t] (bit-exact chain)
            float cs = __fadd_rn(sm, R1v);
            float d1 = __fadd_rn(cs, -f0);
            float d2 = __fmul_rn(d1, TWO_PI_F);
            float d3 = div_full(d2, 16000.0f);         // XLA GPU divide
            float x  = __fadd_rn(d3, pm[l]);
            float v  = __fmul_rn(x, TWO_O_PI);
            float t  = __fadd_rn(v, MAGIC);
            float n  = __fadd_rn(t, -MAGIC);
            int   q  = __float_as_int(t);
            float r  = fmaf(-n, P1, x);
            r        = fmaf(-n, P2, r);
            float sr, cr;
            asm("sin.approx.f32 %0, %1;" : "=f"(sr) : "f"(r));
            asm("cos.approx.f32 %0, %1;" : "=f"(cr) : "f"(r));
            float res = (q & 1) ? cr : sr;
            ov[l] = __int_as_float(__float_as_int(res) ^ ((q & 2) << 30));
        }
        ((float4*)out)[gq] = make_float4(ov[0], ov[1], ov[2], ov[3]);
    }

    // ---------------- replay-safe counter reset ------------------------------
    __syncthreads();
    if (tid == 0) {
        __threadfence();
        unsigned r = atomicAdd(&g_fin, 1u);
        if (r == (unsigned)(GRID - 1)) {
            atomicExch(&g_done, 0u);
            __threadfence();
            atomicExch(&g_fin, 0u);
        }
    }
}

extern "C" void kernel_launch(void* const* d_in, const int* in_sizes, int n_in,
                              void* d_out, int out_size) {
    const float* freq = (const float*)d_in[0];   // [64, 4096]
    const float* pmod = (const float*)d_in[1];   // [64, 262144]
    float* out = (float*)d_out;                  // [64, 262144]

    fused_k<<<GRID, TPB>>>(freq, pmod, out);
}

// round 12
// speedup vs baseline: 1.3896x; 1.3896x over previous
#include <cuda_runtime.h>
#include <cuda_bf16.h>
#include <math.h>

// Oscillator: XLA rw16 cumsum association + div.full.f32 scale chain (bit-exact
// through x); MUFU sin. Single persistent kernel. Prep rebuilt for ILP under the
// 32-reg cap: float4 loads/stores, no sm16 array, aligned offset-table stores.

#define B_DIM 64
#define F_DIM 4096
#define NHOPS (B_DIM * F_DIM)          // 262144
#define NOUT (NHOPS * 64)              // 16777216
#define NQ 16384                       // strips of 16 per row
#define TPB 256
#define GRID (148 * 8)                 // all co-resident (smem 8.6KB*8, regs<=32)
#define NTILES (NOUT / 4 / TPB)        // 16384

__device__ float    g_T[B_DIM * NQ];   // T[q] = (q>0 ? R1[q-1] : 0), strip-aligned
__device__ float4   g_b4[NHOPS];       // per hop: (f, fold4, fold8, fold12)
__device__ unsigned g_done;
__device__ unsigned g_fin;

__device__ __forceinline__ float div_full(float a, float b) {
    float r;
    asm("div.full.f32 %0, %1, %2;" : "=f"(r) : "f"(a), "f"(b));
    return r;
}

__global__ void __launch_bounds__(TPB, 8) fused_k(const float* __restrict__ freq,
                                                  const float* __restrict__ pmod,
                                                  float* __restrict__ out) {
    __shared__ float S1[1024];     // level-1 strip totals
    __shared__ float R2s[1024];    // level-2 inclusive scan
    __shared__ float S2[64];
    __shared__ float I3s[64];
    __shared__ float R3s[64];
    __shared__ float R4s[4];

    const int tid = threadIdx.x;

    // ---------------- Phase A: rw16 tables (blocks 0..63, one row each) ------
    if (blockIdx.x < B_DIM) {
        const int row = blockIdx.x;
        const float4* fr4 = (const float4*)(freq + row * F_DIM);

        // pass 1: per strip a (4 hops): sm16 chains (ILP-4) + b4 + S1
        #pragma unroll
        for (int u = 0; u < 4; u++) {
            const int a = tid + u * TPB;              // strip 0..1023
            const float4 fv = __ldg(&fr4[a]);         // f of hops 4a..4a+3
            float s0 = 0.f, s1 = 0.f, s2 = 0.f, s3 = 0.f;
            float4 b0, b1, b2, b3;
            b0.x = fv.x; b1.x = fv.y; b2.x = fv.z; b3.x = fv.w;
            #pragma unroll
            for (int i = 0; i < 16; i++) {
                s0 = __fadd_rn(s0, fv.x);
                s1 = __fadd_rn(s1, fv.y);
                s2 = __fadd_rn(s2, fv.z);
                s3 = __fadd_rn(s3, fv.w);
                if (i == 3)  { b0.y = s0; b1.y = s1; b2.y = s2; b3.y = s3; }
                if (i == 7)  { b0.z = s0; b1.z = s1; b2.z = s2; b3.z = s3; }
                if (i == 11) { b0.w = s0; b1.w = s1; b2.w = s2; b3.w = s3; }
            }
            float4* bdst = &g_b4[row * F_DIM + 4 * a];
            bdst[0] = b0; bdst[1] = b1; bdst[2] = b2; bdst[3] = b3;
            // S1[a]: fold 16 V1 values (each sm16 used 4x), sequential
            float acc = 0.f;
            #pragma unroll
            for (int i = 0; i < 4; i++) acc = __fadd_rn(acc, s0);
            #pragma unroll
            for (int i = 0; i < 4; i++) acc = __fadd_rn(acc, s1);
            #pragma unroll
            for (int i = 0; i < 4; i++) acc = __fadd_rn(acc, s2);
            #pragma unroll
            for (int i = 0; i < 4; i++) acc = __fadd_rn(acc, s3);
            S1[a] = acc;
        }
        __syncthreads();

        // level-2/3/4 small scans
        if (tid < 64) {
            const float4* s1v = (const float4*)&S1[16 * tid];
            float acc = 0.f;
            #pragma unroll
            for (int i = 0; i < 4; i++) {
                float4 v = s1v[i];
                acc = __fadd_rn(acc, v.x); acc = __fadd_rn(acc, v.y);
                acc = __fadd_rn(acc, v.z); acc = __fadd_rn(acc, v.w);
            }
            S2[tid] = acc;
        }
        __syncthreads();
        if (tid < 4) {
            float acc = 0.f;
            #pragma unroll
            for (int i = 0; i < 16; i++) {
                acc = __fadd_rn(acc, S2[16 * tid + i]);
                I3s[16 * tid + i] = acc;
            }
        }
        __syncthreads();
        if (tid == 0) {
            float acc = 0.f;
            #pragma unroll
            for (int d = 0; d < 4; d++) {
                acc = __fadd_rn(acc, I3s[16 * d + 15]);
                R4s[d] = acc;
            }
        }
        __syncthreads();
        if (tid < 64)
            R3s[tid] = (tid >= 16) ? __fadd_rn(I3s[tid], R4s[(tid >> 4) - 1]) : I3s[tid];
        __syncthreads();
        if (tid < 64) {
            float acc = 0.f;
            #pragma unroll
            for (int i = 0; i < 16; i++) {
                acc = __fadd_rn(acc, S1[16 * tid + i]);
                R2s[16 * tid + i] = (tid > 0) ? __fadd_rn(acc, R3s[tid - 1]) : acc;
            }
        }
        __syncthreads();

        // pass 2: T[16a..16a+15] per strip, aligned float4 stores
        #pragma unroll
        for (int u = 0; u < 4; u++) {
            const int a = tid + u * TPB;
            const float4 fv = __ldg(&fr4[a]);         // L2-hot reload
            float s0 = 0.f, s1 = 0.f, s2 = 0.f, s3 = 0.f;
            #pragma unroll
            for (int i = 0; i < 16; i++) {
                s0 = __fadd_rn(s0, fv.x);
                s1 = __fadd_rn(s1, fv.y);
                s2 = __fadd_rn(s2, fv.z);
                s3 = __fadd_rn(s3, fv.w);
            }
            const float off = (a > 0) ? R2s[a - 1] : 0.0f;
            // boundary: T[16a] = fl(S1[a-1] + off_{a-1}) (0 for a==0)
            float tbuf[16];
            if (a == 0) tbuf[0] = 0.0f;
            else {
                float offp = (a > 1) ? R2s[a - 2] : 0.0f;
                tbuf[0] = __fadd_rn(S1[a - 1], offp);
            }
            float acc = 0.f;
            #pragma unroll
            for (int i = 0; i < 15; i++) {
                float v = (i < 4) ? s0 : (i < 8) ? s1 : (i < 12) ? s2 : s3;
                acc = __fadd_rn(acc, v);
                tbuf[i + 1] = __fadd_rn(acc, off);    // +0 exact when a==0
            }
            float4* tdst = (float4*)&g_T[row * NQ + 16 * a];
            tdst[0] = make_float4(tbuf[0], tbuf[1], tbuf[2], tbuf[3]);
            tdst[1] = make_float4(tbuf[4], tbuf[5], tbuf[6], tbuf[7]);
            tdst[2] = make_float4(tbuf[8], tbuf[9], tbuf[10], tbuf[11]);
            tdst[3] = make_float4(tbuf[12], tbuf[13], tbuf[14], tbuf[15]);
        }
        __threadfence();
        __syncthreads();
        if (tid == 0) atomicAdd(&g_done, 1u);
    }

    // ---------------- grid barrier ------------------------------------------
    if (tid == 0) {
        unsigned v;
        do {
            asm volatile("ld.global.acquire.gpu.u32 %0, [%1];" : "=r"(v) : "l"(&g_done));
            if (v < (unsigned)B_DIM) __nanosleep(64);
        } while (v < (unsigned)B_DIM);
    }
    __syncthreads();

    // ---------------- Phase B: oscillator, grid-stride ----------------------
    const float TWO_PI_F = 6.2831853071795864769f;     // 0x40C90FDB
    const float TWO_O_PI = 0.63661977236758134308f;
    const float MAGIC    = 12582912.0f;                // 1.5 * 2^23
    const float P1 = 1.57079637050628662109375f;
    const float P2 = -4.37113900018624283e-08f;

    for (int tile = blockIdx.x; tile < NTILES; tile += GRID) {
        const int gq  = tile * TPB + tid;
        const int hop = gq >> 4;
        const int s   = gq & 15;
        const int row = gq >> 16;

        const float4 b4 = __ldg(&g_b4[hop]);
        const float  f  = b4.x;
        const float  f0 = __ldg(freq + (row << 12));
        const float  Tv = __ldg(&g_T[row * NQ + ((gq >> 2) & (NQ - 1))]);
        const float4 p4 = __ldg((const float4*)pmod + gq);

        const int s3 = s & 3;
        float aa = (s3 & 1) ? b4.y : 0.0f;
        float bb = (s3 & 1) ? b4.w : b4.z;
        float sm = (s3 & 2) ? bb : aa;

        float pm[4] = {p4.x, p4.y, p4.z, p4.w};
        float ov[4];
        #pragma unroll
        for (int l = 0; l < 4; l++) {
            sm = __fadd_rn(sm, f);                     // I0[t] (bit-exact chain)
            float cs = __fadd_rn(sm, Tv);
            float d1 = __fadd_rn(cs, -f0);
            float d2 = __fmul_rn(d1, TWO_PI_F);
            float d3 = div_full(d2, 16000.0f);         // XLA GPU divide
            float x  = __fadd_rn(d3, pm[l]);
            float v  = __fmul_rn(x, TWO_O_PI);
            float t  = __fadd_rn(v, MAGIC);
            float n  = __fadd_rn(t, -MAGIC);
            int   q  = __float_as_int(t);
            float r  = fmaf(-n, P1, x);
            r        = fmaf(-n, P2, r);
            float sr, cr;
            asm("sin.approx.f32 %0, %1;" : "=f"(sr) : "f"(r));
            asm("cos.approx.f32 %0, %1;" : "=f"(cr) : "f"(r));
            float res = (q & 1) ? cr : sr;
            ov[l] = __int_as_float(__float_as_int(res) ^ ((q & 2) << 30));
        }
        ((float4*)out)[gq] = make_float4(ov[0], ov[1], ov[2], ov[3]);
    }

    // ---------------- replay-safe counter reset -----------------------------
    __syncthreads();
    if (tid == 0) {
        __threadfence();
        unsigned r = atomicAdd(&g_fin, 1u);
        if (r == (unsigned)(GRID - 1)) {
            atomicExch(&g_done, 0u);
            __threadfence();
            atomicExch(&g_fin, 0u);
        }
    }
}

extern "C" void kernel_launch(void* const* d_in, const int* in_sizes, int n_in,
                              void* d_out, int out_size) {
    const float* freq = (const float*)d_in[0];   // [64, 4096]
    const float* pmod = (const float*)d_in[1];   // [64, 262144]
    float* out = (float*)d_out;                  // [64, 262144]

    fused_k<<<GRID, TPB>>>(freq, pmod, out);
}